// round 1
// baseline (speedup 1.0000x reference)
#include <cuda_runtime.h>
#include <math.h>

#define DD 384
#define HH 192
#define NB 64
#define NATOMS 8192
#define IMG (DD*DD)

// Trig / Hartley tables
__device__ float g_C[IMG];
__device__ float g_S[IMG];
__device__ float g_H1[IMG];
__device__ float g_H2[IMG];
// Intermediate complex stage (Tr = C@X, Ti = S@X)
__device__ float g_Tr[NB*IMG];
__device__ float g_Ti[NB*IMG];

// ---------------------------------------------------------------------------
// Build shift-absorbed DFT tables: A[k,n] = exp(-2pi i (k+H)(n+H)/D) = C - i S
// Exponent computed exactly mod D in integers, trig in double.
// ---------------------------------------------------------------------------
__global__ void table_kernel() {
    int i = blockIdx.x * blockDim.x + threadIdx.x;
    if (i >= IMG) return;
    int k = i / DD, n = i % DD;
    int m = ((k + HH) * (n + HH)) % DD;
    double th = (double)m * (2.0 * M_PI / (double)DD);
    float c = (float)cos(th);
    float s = (float)sin(th);
    g_C[i]  = c;
    g_S[i]  = s;
    g_H1[i] = c + s;
    g_H2[i] = c - s;
}

// ---------------------------------------------------------------------------
// Pose transform + gaussian splat. One thread per atom.
// c = x/PIX + D/2 ; patch 11x11 centered at round(c); gx = exp(-(ix-c)^2/(2s^2))
// ---------------------------------------------------------------------------
__global__ void splat_kernel(const float* __restrict__ crd,
                             const float* __restrict__ rot,
                             const float* __restrict__ rot_init,
                             const float* __restrict__ trans_init,
                             float* __restrict__ img) {
    int gid = blockIdx.x * blockDim.x + threadIdx.x;
    if (gid >= NB * NATOMS) return;
    int b = gid >> 13;

    const float* p = crd + (size_t)gid * 3;
    float x0 = p[0], x1 = p[1], x2 = p[2];

    // crd2 = crd @ rot_init + trans_init   (row-vector * matrix)
    float c0 = x0 * __ldg(&rot_init[0]) + x1 * __ldg(&rot_init[3]) + x2 * __ldg(&rot_init[6]) + __ldg(&trans_init[0]);
    float c1 = x0 * __ldg(&rot_init[1]) + x1 * __ldg(&rot_init[4]) + x2 * __ldg(&rot_init[7]) + __ldg(&trans_init[1]);
    float c2 = x0 * __ldg(&rot_init[2]) + x1 * __ldg(&rot_init[5]) + x2 * __ldg(&rot_init[8]) + __ldg(&trans_init[2]);

    // out[k] = sum_j crd2[j] * rot[b,k,j]   (need k = 0,1)
    const float* R = rot + b * 9;
    float fx = c0 * __ldg(&R[0]) + c1 * __ldg(&R[1]) + c2 * __ldg(&R[2]);
    float fy = c0 * __ldg(&R[3]) + c1 * __ldg(&R[4]) + c2 * __ldg(&R[5]);

    float cx = fx + (float)HH;   // PIX = 1
    float cy = fy + (float)HH;
    int ix0 = (int)rintf(cx) - 5;
    int iy0 = (int)rintf(cy) - 5;

    const float inv2s2 = 1.0f / (2.0f * 1.5f * 1.5f);
    float gx[11], gy[11];
#pragma unroll
    for (int t = 0; t < 11; t++) {
        int ix = ix0 + t;
        int iy = iy0 + t;
        float dx = (float)ix - cx;
        float dy = (float)iy - cy;
        gx[t] = ((unsigned)ix < (unsigned)DD) ? expf(-dx * dx * inv2s2) : 0.0f;
        gy[t] = ((unsigned)iy < (unsigned)DD) ? expf(-dy * dy * inv2s2) : 0.0f;
    }

    float* im = img + (size_t)b * IMG;
#pragma unroll
    for (int ty = 0; ty < 11; ty++) {
        float gyv = gy[ty];
        if (gyv == 0.0f) continue;
        int row = iy0 + ty;
        float* imr = im + row * DD + ix0;
#pragma unroll
        for (int tx = 0; tx < 11; tx++) {
            float v = gyv * gx[tx];
            if (v != 0.0f) atomicAdd(&imr[tx], v);
        }
    }
}

// ---------------------------------------------------------------------------
// Stage 1: Tr = C @ X, Ti = S @ X   per batch. 64x64 block tile, 4x4 microtile.
// ---------------------------------------------------------------------------
__global__ void gemm1_kernel(const float* __restrict__ X) {
    __shared__ float sC[64][16];
    __shared__ float sS[64][16];
    __shared__ float sX[16][64];

    const int z  = blockIdx.z;
    const int r0 = blockIdx.y * 64;   // output rows (k)
    const int c0 = blockIdx.x * 64;   // output cols (v)
    const float* Xb = X + (size_t)z * IMG;

    const int t  = threadIdx.x;       // 0..255
    const int ty = t >> 4;
    const int tx = t & 15;

    float accR[4][4] = {};
    float accI[4][4] = {};

    for (int u0 = 0; u0 < DD; u0 += 16) {
#pragma unroll
        for (int i = 0; i < 4; i++) {
            int e   = t + 256 * i;
            int rr  = e >> 4, cc = e & 15;
            sC[rr][cc] = g_C[(r0 + rr) * DD + u0 + cc];
            sS[rr][cc] = g_S[(r0 + rr) * DD + u0 + cc];
            int rr2 = e >> 6, cc2 = e & 63;
            sX[rr2][cc2] = Xb[(u0 + rr2) * DD + c0 + cc2];
        }
        __syncthreads();
#pragma unroll
        for (int kk = 0; kk < 16; kk++) {
            float a[4], s[4], x[4];
#pragma unroll
            for (int i = 0; i < 4; i++) { a[i] = sC[ty * 4 + i][kk]; s[i] = sS[ty * 4 + i][kk]; }
#pragma unroll
            for (int j = 0; j < 4; j++) x[j] = sX[kk][tx * 4 + j];
#pragma unroll
            for (int i = 0; i < 4; i++)
#pragma unroll
                for (int j = 0; j < 4; j++) {
                    accR[i][j] += a[i] * x[j];
                    accI[i][j] += s[i] * x[j];
                }
        }
        __syncthreads();
    }

    float* TrB = g_Tr + (size_t)z * IMG;
    float* TiB = g_Ti + (size_t)z * IMG;
#pragma unroll
    for (int i = 0; i < 4; i++)
#pragma unroll
        for (int j = 0; j < 4; j++) {
            int idx = (r0 + ty * 4 + i) * DD + c0 + tx * 4 + j;
            TrB[idx] = accR[i][j];
            TiB[idx] = accI[i][j];
        }
}

// ---------------------------------------------------------------------------
// Stage 2: y = Tr @ (C+S) + Ti @ (C-S)
// ---------------------------------------------------------------------------
__global__ void gemm2_kernel(float* __restrict__ Y) {
    __shared__ float sA[64][16];   // Tr
    __shared__ float sB[64][16];   // Ti
    __shared__ float s1[16][64];   // H1
    __shared__ float s2[16][64];   // H2

    const int z  = blockIdx.z;
    const int r0 = blockIdx.y * 64;   // output rows (k)
    const int c0 = blockIdx.x * 64;   // output cols (l)
    const float* TrB = g_Tr + (size_t)z * IMG;
    const float* TiB = g_Ti + (size_t)z * IMG;

    const int t  = threadIdx.x;
    const int ty = t >> 4;
    const int tx = t & 15;

    float acc[4][4] = {};

    for (int v0 = 0; v0 < DD; v0 += 16) {
#pragma unroll
        for (int i = 0; i < 4; i++) {
            int e   = t + 256 * i;
            int rr  = e >> 4, cc = e & 15;
            sA[rr][cc] = TrB[(r0 + rr) * DD + v0 + cc];
            sB[rr][cc] = TiB[(r0 + rr) * DD + v0 + cc];
            int rr2 = e >> 6, cc2 = e & 63;
            s1[rr2][cc2] = g_H1[(v0 + rr2) * DD + c0 + cc2];
            s2[rr2][cc2] = g_H2[(v0 + rr2) * DD + c0 + cc2];
        }
        __syncthreads();
#pragma unroll
        for (int kk = 0; kk < 16; kk++) {
            float a[4], b[4], h1[4], h2[4];
#pragma unroll
            for (int i = 0; i < 4; i++) { a[i] = sA[ty * 4 + i][kk]; b[i] = sB[ty * 4 + i][kk]; }
#pragma unroll
            for (int j = 0; j < 4; j++) { h1[j] = s1[kk][tx * 4 + j]; h2[j] = s2[kk][tx * 4 + j]; }
#pragma unroll
            for (int i = 0; i < 4; i++)
#pragma unroll
                for (int j = 0; j < 4; j++)
                    acc[i][j] += a[i] * h1[j] + b[i] * h2[j];
        }
        __syncthreads();
    }

    float* Yb = Y + (size_t)z * IMG;
#pragma unroll
    for (int i = 0; i < 4; i++)
#pragma unroll
        for (int j = 0; j < 4; j++)
            Yb[(r0 + ty * 4 + i) * DD + c0 + tx * 4 + j] = acc[i][j];
}

// ---------------------------------------------------------------------------
extern "C" void kernel_launch(void* const* d_in, const int* in_sizes, int n_in,
                              void* d_out, int out_size) {
    // Identify inputs by element count (robust to ordering):
    // crd: 64*8192*3 = 1572864, rot: 576, rot_init: 9, trans_init: 3
    const float* crd = nullptr;
    const float* rot = nullptr;
    const float* rot_init = nullptr;
    const float* trans_init = nullptr;
    for (int i = 0; i < n_in; i++) {
        switch (in_sizes[i]) {
            case 1572864: crd        = (const float*)d_in[i]; break;
            case 576:     rot        = (const float*)d_in[i]; break;
            case 9:       rot_init   = (const float*)d_in[i]; break;
            case 3:       trans_init = (const float*)d_in[i]; break;
            default: break;
        }
    }

    float* y = (float*)d_out;
    size_t half = (size_t)out_size / 2;       // = 64*384*384
    float* y_real = y + half;

    // zero the splat target (d_out is poisoned)
    cudaMemsetAsync(y_real, 0, half * sizeof(float));

    table_kernel<<<(IMG + 255) / 256, 256>>>();

    splat_kernel<<<(NB * NATOMS + 255) / 256, 256>>>(crd, rot, rot_init, trans_init, y_real);

    dim3 g(DD / 64, DD / 64, NB);   // 6 x 6 x 64
    gemm1_kernel<<<g, 256>>>(y_real);
    gemm2_kernel<<<g, 256>>>(y);
}

// round 2
// speedup vs baseline: 1.6147x; 1.6147x over previous
#include <cuda_runtime.h>
#include <math.h>

#define DD 384
#define HH 192
#define NB 64
#define NATOMS 8192
#define IMG (DD*DD)
#define MROWS 192   // rows 0..191 computed by GEMMs; row 192 special; 193..383 mirrored

// Trig / Hartley tables (all symmetric: M[k,n] == M[n,k])
__device__ float g_C[IMG];
__device__ float g_S[IMG];
__device__ float g_H1[IMG];   // C + S
__device__ float g_H2[IMG];   // C - S
// Intermediate stage (rows 0..191 only): Tr = C@X, Ti = S@X
__device__ float g_Tr[NB*MROWS*DD];
__device__ float g_Ti[NB*MROWS*DD];
// Row-192 of Tr (= column sums of X), per batch
__device__ float g_T192[NB*DD];

// ---------------------------------------------------------------------------
// A[k,n] = exp(-2pi i (k+H)(n+H)/D) = C - i S ; exponent exact mod D.
// ---------------------------------------------------------------------------
__global__ void table_kernel() {
    int i = blockIdx.x * blockDim.x + threadIdx.x;
    if (i >= IMG) return;
    int k = i / DD, n = i % DD;
    int m = ((k + HH) * (n + HH)) % DD;
    double th = (double)m * (2.0 * M_PI / (double)DD);
    float c = (float)cos(th);
    float s = (float)sin(th);
    g_C[i]  = c;
    g_S[i]  = s;
    g_H1[i] = c + s;
    g_H2[i] = c - s;
}

// ---------------------------------------------------------------------------
// Pose transform + gaussian splat. One thread per atom.
// ---------------------------------------------------------------------------
__global__ void splat_kernel(const float* __restrict__ crd,
                             const float* __restrict__ rot,
                             const float* __restrict__ rot_init,
                             const float* __restrict__ trans_init,
                             float* __restrict__ img) {
    int gid = blockIdx.x * blockDim.x + threadIdx.x;
    if (gid >= NB * NATOMS) return;
    int b = gid >> 13;

    const float* p = crd + (size_t)gid * 3;
    float x0 = p[0], x1 = p[1], x2 = p[2];

    float c0 = x0 * __ldg(&rot_init[0]) + x1 * __ldg(&rot_init[3]) + x2 * __ldg(&rot_init[6]) + __ldg(&trans_init[0]);
    float c1 = x0 * __ldg(&rot_init[1]) + x1 * __ldg(&rot_init[4]) + x2 * __ldg(&rot_init[7]) + __ldg(&trans_init[1]);
    float c2 = x0 * __ldg(&rot_init[2]) + x1 * __ldg(&rot_init[5]) + x2 * __ldg(&rot_init[8]) + __ldg(&trans_init[2]);

    const float* R = rot + b * 9;
    float fx = c0 * __ldg(&R[0]) + c1 * __ldg(&R[1]) + c2 * __ldg(&R[2]);
    float fy = c0 * __ldg(&R[3]) + c1 * __ldg(&R[4]) + c2 * __ldg(&R[5]);

    float cx = fx + (float)HH;
    float cy = fy + (float)HH;
    int ix0 = (int)rintf(cx) - 5;
    int iy0 = (int)rintf(cy) - 5;

    const float inv2s2 = 1.0f / (2.0f * 1.5f * 1.5f);
    float gx[11], gy[11];
#pragma unroll
    for (int t = 0; t < 11; t++) {
        int ix = ix0 + t;
        int iy = iy0 + t;
        float dx = (float)ix - cx;
        float dy = (float)iy - cy;
        gx[t] = ((unsigned)ix < (unsigned)DD) ? expf(-dx * dx * inv2s2) : 0.0f;
        gy[t] = ((unsigned)iy < (unsigned)DD) ? expf(-dy * dy * inv2s2) : 0.0f;
    }

    float* im = img + (size_t)b * IMG;
#pragma unroll
    for (int ty = 0; ty < 11; ty++) {
        float gyv = gy[ty];
        if (gyv == 0.0f) continue;
        int row = iy0 + ty;
        float* imr = im + row * DD + ix0;
#pragma unroll
        for (int tx = 0; tx < 11; tx++) {
            float v = gyv * gx[tx];
            if (v != 0.0f) atomicAdd(&imr[tx], v);
        }
    }
}

// ---------------------------------------------------------------------------
// Column sums of X per batch -> g_T192 (this is Tr row 192 since C[192,:]=1)
// ---------------------------------------------------------------------------
__global__ void colsum_kernel(const float* __restrict__ X) {
    int b = blockIdx.y;
    int v = blockIdx.x * blockDim.x + threadIdx.x;
    if (v >= DD) return;
    const float* Xb = X + (size_t)b * IMG;
    float acc = 0.0f;
    for (int u = 0; u < DD; u++) acc += Xb[u * DD + v];
    g_T192[b * DD + v] = acc;
}

// ---------------------------------------------------------------------------
// Y[b][192][l] = sum_v T192[b][v] * H1[v][l]   (Ti row 192 is 0)
// ---------------------------------------------------------------------------
__global__ void row192_kernel(float* __restrict__ Y) {
    int b = blockIdx.y;
    int l = blockIdx.x * blockDim.x + threadIdx.x;
    if (l >= DD) return;
    const float* t = g_T192 + b * DD;
    float acc = 0.0f;
    for (int v = 0; v < DD; v++) acc += t[v] * g_H1[v * DD + l];
    Y[(size_t)b * IMG + 192 * DD + l] = acc;
}

// ---------------------------------------------------------------------------
// Stage 1: Tr = C @ X, Ti = S @ X for rows 0..191.
// C and S are SYMMETRIC, so the k-major smem tile sC[uu][rr] = C[r0+rr][u0+uu]
// = C[u0+uu][r0+rr] stages with coalesced row-major reads, and both operand
// fragments become LDS.128.
// ---------------------------------------------------------------------------
__global__ void gemm1_kernel(const float* __restrict__ X) {
    __shared__ float sC[16][64];
    __shared__ float sS[16][64];
    __shared__ float sX[16][64];

    const int z  = blockIdx.z;
    const int r0 = blockIdx.y * 64;   // 0,64,128 -> rows 0..191
    const int c0 = blockIdx.x * 64;
    const float* Xb = X + (size_t)z * IMG;

    const int t  = threadIdx.x;       // 0..255
    const int ty = t >> 4;
    const int tx = t & 15;

    float accR[4][4] = {};
    float accI[4][4] = {};

    for (int u0 = 0; u0 < DD; u0 += 16) {
#pragma unroll
        for (int i = 0; i < 4; i++) {
            int e  = t + 256 * i;
            int uu = e >> 6, cc = e & 63;
            sC[uu][cc] = g_C[(u0 + uu) * DD + r0 + cc];
            sS[uu][cc] = g_S[(u0 + uu) * DD + r0 + cc];
            sX[uu][cc] = Xb[(u0 + uu) * DD + c0 + cc];
        }
        __syncthreads();
#pragma unroll
        for (int kk = 0; kk < 16; kk++) {
            float4 a4 = *reinterpret_cast<const float4*>(&sC[kk][ty * 4]);
            float4 s4 = *reinterpret_cast<const float4*>(&sS[kk][ty * 4]);
            float4 x4 = *reinterpret_cast<const float4*>(&sX[kk][tx * 4]);
            float a[4] = {a4.x, a4.y, a4.z, a4.w};
            float s[4] = {s4.x, s4.y, s4.z, s4.w};
            float x[4] = {x4.x, x4.y, x4.z, x4.w};
#pragma unroll
            for (int i = 0; i < 4; i++)
#pragma unroll
                for (int j = 0; j < 4; j++) {
                    accR[i][j] += a[i] * x[j];
                    accI[i][j] += s[i] * x[j];
                }
        }
        __syncthreads();
    }

    float* TrB = g_Tr + (size_t)z * MROWS * DD;
    float* TiB = g_Ti + (size_t)z * MROWS * DD;
#pragma unroll
    for (int i = 0; i < 4; i++) {
        int row = r0 + ty * 4 + i;
        float4 r4 = make_float4(accR[i][0], accR[i][1], accR[i][2], accR[i][3]);
        float4 i4 = make_float4(accI[i][0], accI[i][1], accI[i][2], accI[i][3]);
        *reinterpret_cast<float4*>(&TrB[row * DD + c0 + tx * 4]) = r4;
        *reinterpret_cast<float4*>(&TiB[row * DD + c0 + tx * 4]) = i4;
    }
}

// ---------------------------------------------------------------------------
// Stage 2: P = Tr @ H1, Q = Ti @ H2 for rows 0..191.
//   Y[k]      = P + Q
//   Y[384-k]  = P - Q   (k >= 1; uses Tr even / Ti odd symmetry)
// H1/H2 symmetric -> k-major staging with coalesced reads, LDS.128 fragments.
// ---------------------------------------------------------------------------
__global__ void gemm2_kernel(float* __restrict__ Y) {
    __shared__ float sA[64][16];   // Tr tile, row-major (a-frag is broadcast load)
    __shared__ float sB[64][16];   // Ti tile
    __shared__ float s1[16][64];   // H1 k-major
    __shared__ float s2[16][64];   // H2 k-major

    const int z  = blockIdx.z;
    const int r0 = blockIdx.y * 64;   // 0,64,128
    const int c0 = blockIdx.x * 64;
    const float* TrB = g_Tr + (size_t)z * MROWS * DD;
    const float* TiB = g_Ti + (size_t)z * MROWS * DD;

    const int t  = threadIdx.x;
    const int ty = t >> 4;
    const int tx = t & 15;

    float accP[4][4] = {};
    float accQ[4][4] = {};

    for (int v0 = 0; v0 < DD; v0 += 16) {
#pragma unroll
        for (int i = 0; i < 4; i++) {
            int e  = t + 256 * i;
            int rr = e >> 4, kc = e & 15;
            sA[rr][kc] = TrB[(r0 + rr) * DD + v0 + kc];
            sB[rr][kc] = TiB[(r0 + rr) * DD + v0 + kc];
            int vv = e >> 6, ll = e & 63;
            s1[vv][ll] = g_H1[(v0 + vv) * DD + c0 + ll];
            s2[vv][ll] = g_H2[(v0 + vv) * DD + c0 + ll];
        }
        __syncthreads();
#pragma unroll
        for (int kk = 0; kk < 16; kk++) {
            float a[4], b[4];
#pragma unroll
            for (int i = 0; i < 4; i++) { a[i] = sA[ty * 4 + i][kk]; b[i] = sB[ty * 4 + i][kk]; }
            float4 h14 = *reinterpret_cast<const float4*>(&s1[kk][tx * 4]);
            float4 h24 = *reinterpret_cast<const float4*>(&s2[kk][tx * 4]);
            float h1[4] = {h14.x, h14.y, h14.z, h14.w};
            float h2[4] = {h24.x, h24.y, h24.z, h24.w};
#pragma unroll
            for (int i = 0; i < 4; i++)
#pragma unroll
                for (int j = 0; j < 4; j++) {
                    accP[i][j] += a[i] * h1[j];
                    accQ[i][j] += b[i] * h2[j];
                }
        }
        __syncthreads();
    }

    float* Yb = Y + (size_t)z * IMG;
#pragma unroll
    for (int i = 0; i < 4; i++) {
        int k = r0 + ty * 4 + i;
        float4 p4, m4;
        p4.x = accP[i][0] + accQ[i][0];  m4.x = accP[i][0] - accQ[i][0];
        p4.y = accP[i][1] + accQ[i][1];  m4.y = accP[i][1] - accQ[i][1];
        p4.z = accP[i][2] + accQ[i][2];  m4.z = accP[i][2] - accQ[i][2];
        p4.w = accP[i][3] + accQ[i][3];  m4.w = accP[i][3] - accQ[i][3];
        *reinterpret_cast<float4*>(&Yb[k * DD + c0 + tx * 4]) = p4;
        if (k >= 1)
            *reinterpret_cast<float4*>(&Yb[(DD - k) * DD + c0 + tx * 4]) = m4;
    }
}

// ---------------------------------------------------------------------------
extern "C" void kernel_launch(void* const* d_in, const int* in_sizes, int n_in,
                              void* d_out, int out_size) {
    const float* crd = nullptr;
    const float* rot = nullptr;
    const float* rot_init = nullptr;
    const float* trans_init = nullptr;
    for (int i = 0; i < n_in; i++) {
        switch (in_sizes[i]) {
            case 1572864: crd        = (const float*)d_in[i]; break;
            case 576:     rot        = (const float*)d_in[i]; break;
            case 9:       rot_init   = (const float*)d_in[i]; break;
            case 3:       trans_init = (const float*)d_in[i]; break;
            default: break;
        }
    }

    float* y = (float*)d_out;
    size_t half = (size_t)out_size / 2;   // 64*384*384
    float* y_real = y + half;

    cudaMemsetAsync(y_real, 0, half * sizeof(float));

    table_kernel<<<(IMG + 255) / 256, 256>>>();

    splat_kernel<<<(NB * NATOMS + 255) / 256, 256>>>(crd, rot, rot_init, trans_init, y_real);

    dim3 g1(DD / 64, MROWS / 64, NB);   // 6 x 3 x 64
    gemm1_kernel<<<g1, 256>>>(y_real);

    dim3 gc((DD + 127) / 128, NB);
    colsum_kernel<<<gc, 128>>>(y_real);

    gemm2_kernel<<<g1, 256>>>(y);

    row192_kernel<<<gc, 128>>>(y);
}

// round 4
// speedup vs baseline: 2.1729x; 1.3457x over previous
#include <cuda_runtime.h>
#include <cuda_bf16.h>
#include <math.h>
#include <stdint.h>

#define DD 384
#define HH 192
#define NB 64
#define NATOMS 8192
#define IMG (DD*DD)
#define K1 256            // stage-1 folded K (208) padded to 256
#define MR 192            // rows 0..191 via GEMM; 192 special; 193..383 mirrored

// ---------------- device scratch -------------------------------------------
__device__ __align__(16) __nv_bfloat16 g_Cb_h[MR*K1], g_Cb_l[MR*K1];
__device__ __align__(16) __nv_bfloat16 g_Sb_h[MR*K1], g_Sb_l[MR*K1];
__device__ __align__(16) __nv_bfloat16 g_H1b_h[IMG], g_H1b_l[IMG];
__device__ __align__(16) __nv_bfloat16 g_H2b_h[IMG], g_H2b_l[IMG];
__device__ float g_H1f[IMG];
__device__ __align__(16) __nv_bfloat16 g_XeT_h[NB*DD*K1], g_XeT_l[NB*DD*K1];
__device__ __align__(16) __nv_bfloat16 g_XoT_h[NB*DD*K1], g_XoT_l[NB*DD*K1];
__device__ __align__(16) __nv_bfloat16 g_Trb_h[NB*MR*DD], g_Trb_l[NB*MR*DD];
__device__ __align__(16) __nv_bfloat16 g_Tib_h[NB*MR*DD], g_Tib_l[NB*MR*DD];
__device__ float g_T192[NB*DD];

// ---------------- helpers ----------------------------------------------------
__device__ __forceinline__ void split_bf16(float x, __nv_bfloat16& h, __nv_bfloat16& l) {
    h = __float2bfloat16_rn(x);
    l = __float2bfloat16_rn(x - __bfloat162float(h));
}
__device__ __forceinline__ uint32_t smem_u32(const void* p) {
    uint32_t a;
    asm("{ .reg .u64 t; cvta.to.shared.u64 t, %1; cvt.u32.u64 %0, t; }" : "=r"(a) : "l"(p));
    return a;
}
__device__ __forceinline__ uint32_t swz(uint32_t boff) {   // 128B-row swizzle
    return boff ^ ((boff >> 3) & 0x70);
}
__device__ __forceinline__ void ldsm_x4(uint32_t addr, uint32_t* r) {
    asm volatile("ldmatrix.sync.aligned.m8n8.x4.shared.b16 {%0,%1,%2,%3}, [%4];"
                 : "=r"(r[0]), "=r"(r[1]), "=r"(r[2]), "=r"(r[3]) : "r"(addr));
}
__device__ __forceinline__ void ldsm_x2(uint32_t addr, uint32_t* r) {
    asm volatile("ldmatrix.sync.aligned.m8n8.x2.shared.b16 {%0,%1}, [%2];"
                 : "=r"(r[0]), "=r"(r[1]) : "r"(addr));
}
__device__ __forceinline__ void mma_bf16(float* c, const uint32_t* a, const uint32_t* b) {
    asm volatile("mma.sync.aligned.m16n8k16.row.col.f32.bf16.bf16.f32 "
                 "{%0,%1,%2,%3},{%4,%5,%6,%7},{%8,%9},{%0,%1,%2,%3};"
                 : "+f"(c[0]), "+f"(c[1]), "+f"(c[2]), "+f"(c[3])
                 : "r"(a[0]), "r"(a[1]), "r"(a[2]), "r"(a[3]), "r"(b[0]), "r"(b[1]));
}

// ---------------- table prep -------------------------------------------------
__global__ void tableA_kernel() {   // stage-1 coefficients, K-folded, zero-padded
    int i = blockIdx.x * blockDim.x + threadIdx.x;
    if (i >= MR * K1) return;
    int k = i >> 8, u = i & 255;
    float c = 0.f, s = 0.f;
    if (u <= 192) {
        int m = ((k + HH) * (u + HH)) % DD;
        double th = (double)m * (2.0 * M_PI / (double)DD);
        c = (float)cos(th); s = (float)sin(th);
    }
    split_bf16(c, g_Cb_h[i], g_Cb_l[i]);
    split_bf16(s, g_Sb_h[i], g_Sb_l[i]);
}
__global__ void tableH_kernel() {   // Hartley matrices (symmetric 384x384)
    int i = blockIdx.x * blockDim.x + threadIdx.x;
    if (i >= IMG) return;
    int v = i / DD, l = i % DD;
    int m = ((v + HH) * (l + HH)) % DD;
    double th = (double)m * (2.0 * M_PI / (double)DD);
    float c = (float)cos(th), s = (float)sin(th);
    split_bf16(c + s, g_H1b_h[i], g_H1b_l[i]);
    split_bf16(c - s, g_H2b_h[i], g_H2b_l[i]);
    g_H1f[i] = c + s;
}

// ---------------- splat ------------------------------------------------------
__global__ void splat_kernel(const float* __restrict__ crd,
                             const float* __restrict__ rot,
                             const float* __restrict__ rot_init,
                             const float* __restrict__ trans_init,
                             float* __restrict__ img) {
    int gid = blockIdx.x * blockDim.x + threadIdx.x;
    if (gid >= NB * NATOMS) return;
    int b = gid >> 13;
    const float* p = crd + (size_t)gid * 3;
    float x0 = p[0], x1 = p[1], x2 = p[2];
    float c0 = x0 * __ldg(&rot_init[0]) + x1 * __ldg(&rot_init[3]) + x2 * __ldg(&rot_init[6]) + __ldg(&trans_init[0]);
    float c1 = x0 * __ldg(&rot_init[1]) + x1 * __ldg(&rot_init[4]) + x2 * __ldg(&rot_init[7]) + __ldg(&trans_init[1]);
    float c2 = x0 * __ldg(&rot_init[2]) + x1 * __ldg(&rot_init[5]) + x2 * __ldg(&rot_init[8]) + __ldg(&trans_init[2]);
    const float* R = rot + b * 9;
    float fx = c0 * __ldg(&R[0]) + c1 * __ldg(&R[1]) + c2 * __ldg(&R[2]);
    float fy = c0 * __ldg(&R[3]) + c1 * __ldg(&R[4]) + c2 * __ldg(&R[5]);
    float cx = fx + (float)HH, cy = fy + (float)HH;
    int ix0 = (int)rintf(cx) - 5, iy0 = (int)rintf(cy) - 5;
    const float inv2s2 = 1.0f / (2.0f * 1.5f * 1.5f);
    float gx[11], gy[11];
#pragma unroll
    for (int t = 0; t < 11; t++) {
        int ix = ix0 + t, iy = iy0 + t;
        float dx = (float)ix - cx, dy = (float)iy - cy;
        gx[t] = ((unsigned)ix < (unsigned)DD) ? expf(-dx * dx * inv2s2) : 0.0f;
        gy[t] = ((unsigned)iy < (unsigned)DD) ? expf(-dy * dy * inv2s2) : 0.0f;
    }
    float* im = img + (size_t)b * IMG;
#pragma unroll
    for (int ty = 0; ty < 11; ty++) {
        float gyv = gy[ty];
        if (gyv == 0.0f) continue;
        float* imr = im + (iy0 + ty) * DD + ix0;
#pragma unroll
        for (int tx = 0; tx < 11; tx++) {
            float v = gyv * gx[tx];
            if (v != 0.0f) atomicAdd(&imr[tx], v);
        }
    }
}

// ---------------- fold + transpose X -> XeT/XoT bf16 hi/lo ------------------
__global__ void fold_kernel(const float* __restrict__ X) {
    __shared__ float se[32][33];
    __shared__ float so[32][33];
    int z = blockIdx.z;
    int u0 = blockIdx.y * 32;
    int v0 = blockIdx.x * 32;
    const float* Xb = X + (size_t)z * IMG;
#pragma unroll
    for (int r = 0; r < 4; r++) {
        int uu = u0 + threadIdx.y + r * 8;
        int vv = v0 + threadIdx.x;
        float e = 0.f, o = 0.f;
        if (uu == 0) { e = Xb[vv]; }
        else if (uu < 192) { float a = Xb[uu * DD + vv], bm = Xb[(DD - uu) * DD + vv]; e = a + bm; o = a - bm; }
        else if (uu == 192) { e = Xb[192 * DD + vv]; }
        se[threadIdx.y + r * 8][threadIdx.x] = e;
        so[threadIdx.y + r * 8][threadIdx.x] = o;
    }
    __syncthreads();
#pragma unroll
    for (int r = 0; r < 4; r++) {
        int vv = v0 + threadIdx.y + r * 8;
        int uu = u0 + threadIdx.x;
        float e = se[threadIdx.x][threadIdx.y + r * 8];
        float o = so[threadIdx.x][threadIdx.y + r * 8];
        size_t off = ((size_t)z * DD + vv) * K1 + uu;
        split_bf16(e, g_XeT_h[off], g_XeT_l[off]);
        split_bf16(o, g_XoT_h[off], g_XoT_l[off]);
    }
}

// ---------------- colsum (Tr row 192) + Y row 192 ---------------------------
__global__ void colsum_kernel(const float* __restrict__ X) {
    int b = blockIdx.y;
    int v = blockIdx.x * blockDim.x + threadIdx.x;
    if (v >= DD) return;
    const float* Xb = X + (size_t)b * IMG;
    float acc = 0.0f;
    for (int u = 0; u < DD; u++) acc += Xb[u * DD + v];
    g_T192[b * DD + v] = acc;
}
__global__ void row192_kernel(float* __restrict__ Y) {
    int b = blockIdx.y;
    int l = blockIdx.x * blockDim.x + threadIdx.x;
    if (l >= DD) return;
    const float* t = g_T192 + b * DD;
    float acc = 0.0f;
    for (int v = 0; v < DD; v++) acc += t[v] * g_H1f[v * DD + l];
    Y[(size_t)b * IMG + 192 * DD + l] = acc;
}

// ---------------- generic split-precision HMMA GEMM -------------------------
// Block: 256 thr = 8 warps (2 M x 4 N), block tile 64x128, warp tile 32x32.
// Two outputs per warp: out0 = A0@B0, out1 = A1@B1 (3-term bf16 split each).
// MODE 0 (stage 1): A0=C, A1=S [m][k] lda=K1 ; B0=XeT, B1=XoT [n][k] ldb=K1
//                   epilogue: split-write Tr/Ti bf16 hi/lo.
// MODE 1 (stage 2): A0=Tr, A1=Ti lda=DD ; B0=H1, B1=H2 (symmetric) ldb=DD
//                   epilogue: Y[row]=P+Q, Y[384-row]=P-Q.
// smem: A sets 4 x 8KB @0, B sets 4 x 16KB @32768. Total 96KB.
template<int MODE>
__global__ __launch_bounds__(256, 1) void mma_gemm_kernel(float* __restrict__ Y) {
    extern __shared__ char smem[];
    uint32_t sb = smem_u32(smem);
    const int t = threadIdx.x;
    const int lane = t & 31, wid = t >> 5;
    const int wm = wid >> 2, wn = wid & 3;
    const int z = blockIdx.z, m0 = blockIdx.y * 64, n0 = blockIdx.x * 128;

    const int KCH = (MODE == 0) ? 4 : 6;
    const int LDA = (MODE == 0) ? K1 : DD;
    const int LDB = (MODE == 0) ? K1 : DD;

    const __nv_bfloat16* Asrc[4];
    const __nv_bfloat16* Bsrc[4];
    if (MODE == 0) {
        Asrc[0] = g_Cb_h + (size_t)m0 * K1;  Asrc[1] = g_Cb_l + (size_t)m0 * K1;
        Asrc[2] = g_Sb_h + (size_t)m0 * K1;  Asrc[3] = g_Sb_l + (size_t)m0 * K1;
        size_t bo = ((size_t)z * DD + n0) * K1;
        Bsrc[0] = g_XeT_h + bo; Bsrc[1] = g_XeT_l + bo;
        Bsrc[2] = g_XoT_h + bo; Bsrc[3] = g_XoT_l + bo;
    } else {
        size_t ao = ((size_t)z * MR + m0) * DD;
        Asrc[0] = g_Trb_h + ao; Asrc[1] = g_Trb_l + ao;
        Asrc[2] = g_Tib_h + ao; Asrc[3] = g_Tib_l + ao;
        size_t bo = (size_t)n0 * DD;
        Bsrc[0] = g_H1b_h + bo; Bsrc[1] = g_H1b_l + bo;
        Bsrc[2] = g_H2b_h + bo; Bsrc[3] = g_H2b_l + bo;
    }

    float acc[2][2][4][4];
#pragma unroll
    for (int o = 0; o < 2; o++)
#pragma unroll
        for (int mt = 0; mt < 2; mt++)
#pragma unroll
            for (int nt = 0; nt < 4; nt++)
#pragma unroll
                for (int r = 0; r < 4; r++) acc[o][mt][nt][r] = 0.f;

    // ldmatrix lane geometry
    const int a_row = wm * 32 + (lane & 7) + ((lane >> 3) & 1) * 8;   // + mt*16
    const int a_kb  = (lane >> 4) * 16;                                // + k16*32
    const int b_row = wn * 32 + (lane & 7);                            // + nt*8
    const int b_kb  = (((lane & 15) >> 3)) * 16;                       // + k16*32

    for (int kc = 0; kc < KCH; kc++) {
        // stage tiles into swizzled smem
#pragma unroll
        for (int s = 0; s < 4; s++) {
#pragma unroll
            for (int j = 0; j < 2; j++) {        // A: 64 rows x 8 chunks
                int cid = t + 256 * j;
                int row = cid >> 3, c = cid & 7;
                uint4 v = *reinterpret_cast<const uint4*>(Asrc[s] + (size_t)row * LDA + kc * 64 + c * 8);
                uint32_t dst = sb + s * 8192u + swz((uint32_t)row * 128u + (uint32_t)c * 16u);
                asm volatile("st.shared.v4.b32 [%0], {%1,%2,%3,%4};"
                             :: "r"(dst), "r"(v.x), "r"(v.y), "r"(v.z), "r"(v.w));
            }
#pragma unroll
            for (int j = 0; j < 4; j++) {        // B: 128 rows x 8 chunks
                int cid = t + 256 * j;
                int row = cid >> 3, c = cid & 7;
                uint4 v = *reinterpret_cast<const uint4*>(Bsrc[s] + (size_t)row * LDB + kc * 64 + c * 8);
                uint32_t dst = sb + 32768u + s * 16384u + swz((uint32_t)row * 128u + (uint32_t)c * 16u);
                asm volatile("st.shared.v4.b32 [%0], {%1,%2,%3,%4};"
                             :: "r"(dst), "r"(v.x), "r"(v.y), "r"(v.z), "r"(v.w));
            }
        }
        __syncthreads();

#pragma unroll
        for (int k16 = 0; k16 < 4; k16++) {
            uint32_t a[4][2][4], b[4][4][2];
#pragma unroll
            for (int s = 0; s < 4; s++)
#pragma unroll
                for (int mt = 0; mt < 2; mt++) {
                    uint32_t bo = (uint32_t)(a_row + mt * 16) * 128u + (uint32_t)(k16 * 32 + a_kb);
                    ldsm_x4(sb + s * 8192u + swz(bo), a[s][mt]);
                }
#pragma unroll
            for (int s = 0; s < 4; s++)
#pragma unroll
                for (int nt = 0; nt < 4; nt++) {
                    uint32_t bo = (uint32_t)(b_row + nt * 8) * 128u + (uint32_t)(k16 * 32 + b_kb);
                    ldsm_x2(sb + 32768u + s * 16384u + swz(bo), b[s][nt]);
                }
#pragma unroll
            for (int mt = 0; mt < 2; mt++)
#pragma unroll
                for (int nt = 0; nt < 4; nt++) {
                    mma_bf16(acc[0][mt][nt], a[0][mt], b[0][nt]);   // hi*hi
                    mma_bf16(acc[0][mt][nt], a[0][mt], b[1][nt]);   // hi*lo
                    mma_bf16(acc[0][mt][nt], a[1][mt], b[0][nt]);   // lo*hi
                    mma_bf16(acc[1][mt][nt], a[2][mt], b[2][nt]);
                    mma_bf16(acc[1][mt][nt], a[2][mt], b[3][nt]);
                    mma_bf16(acc[1][mt][nt], a[3][mt], b[2][nt]);
                }
        }
        __syncthreads();
    }

    // epilogue
    const int gr = lane >> 2, gc = 2 * (lane & 3);
    if (MODE == 0) {
#pragma unroll
        for (int mt = 0; mt < 2; mt++)
#pragma unroll
            for (int nt = 0; nt < 4; nt++) {
                int col = n0 + wn * 32 + nt * 8 + gc;
#pragma unroll
                for (int h = 0; h < 2; h++) {
                    int row = m0 + wm * 32 + mt * 16 + gr + h * 8;
                    size_t off = ((size_t)z * MR + row) * DD + col;
                    __nv_bfloat16 h0, l0, h1, l1;
                    split_bf16(acc[0][mt][nt][h * 2],     h0, l0);
                    split_bf16(acc[0][mt][nt][h * 2 + 1], h1, l1);
                    __nv_bfloat162 hh; hh.x = h0; hh.y = h1;
                    __nv_bfloat162 ll; ll.x = l0; ll.y = l1;
                    *reinterpret_cast<__nv_bfloat162*>(&g_Trb_h[off]) = hh;
                    *reinterpret_cast<__nv_bfloat162*>(&g_Trb_l[off]) = ll;
                    split_bf16(acc[1][mt][nt][h * 2],     h0, l0);
                    split_bf16(acc[1][mt][nt][h * 2 + 1], h1, l1);
                    hh.x = h0; hh.y = h1; ll.x = l0; ll.y = l1;
                    *reinterpret_cast<__nv_bfloat162*>(&g_Tib_h[off]) = hh;
                    *reinterpret_cast<__nv_bfloat162*>(&g_Tib_l[off]) = ll;
                }
            }
    } else {
        float* Yb = Y + (size_t)z * IMG;
#pragma unroll
        for (int mt = 0; mt < 2; mt++)
#pragma unroll
            for (int nt = 0; nt < 4; nt++) {
                int col = n0 + wn * 32 + nt * 8 + gc;
#pragma unroll
                for (int h = 0; h < 2; h++) {
                    int row = m0 + wm * 32 + mt * 16 + gr + h * 8;
                    float p0 = acc[0][mt][nt][h * 2],     q0 = acc[1][mt][nt][h * 2];
                    float p1 = acc[0][mt][nt][h * 2 + 1], q1 = acc[1][mt][nt][h * 2 + 1];
                    float2 yp; yp.x = p0 + q0; yp.y = p1 + q1;
                    *reinterpret_cast<float2*>(&Yb[(size_t)row * DD + col]) = yp;
                    if (row >= 1) {
                        float2 ym; ym.x = p0 - q0; ym.y = p1 - q1;
                        *reinterpret_cast<float2*>(&Yb[(size_t)(DD - row) * DD + col]) = ym;
                    }
                }
            }
    }
}

#define SMEM_BYTES (32768 + 4*16384)

// ---------------------------------------------------------------------------
extern "C" void kernel_launch(void* const* d_in, const int* in_sizes, int n_in,
                              void* d_out, int out_size) {
    const float* crd = nullptr;
    const float* rot = nullptr;
    const float* rot_init = nullptr;
    const float* trans_init = nullptr;
    for (int i = 0; i < n_in; i++) {
        switch (in_sizes[i]) {
            case 1572864: crd        = (const float*)d_in[i]; break;
            case 576:     rot        = (const float*)d_in[i]; break;
            case 9:       rot_init   = (const float*)d_in[i]; break;
            case 3:       trans_init = (const float*)d_in[i]; break;
            default: break;
        }
    }

    float* y = (float*)d_out;
    size_t half = (size_t)out_size / 2;   // 64*384*384
    float* y_real = y + half;

    cudaFuncSetAttribute(mma_gemm_kernel<0>, cudaFuncAttributeMaxDynamicSharedMemorySize, SMEM_BYTES);
    cudaFuncSetAttribute(mma_gemm_kernel<1>, cudaFuncAttributeMaxDynamicSharedMemorySize, SMEM_BYTES);

    cudaMemsetAsync(y_real, 0, half * sizeof(float));

    tableA_kernel<<<(MR * K1 + 255) / 256, 256>>>();
    tableH_kernel<<<(IMG + 255) / 256, 256>>>();

    splat_kernel<<<(NB * NATOMS + 255) / 256, 256>>>(crd, rot, rot_init, trans_init, y_real);

    dim3 gf(DD / 32, K1 / 32, NB);        // 12 x 8 x 64
    fold_kernel<<<gf, dim3(32, 8)>>>(y_real);

    dim3 gc((DD + 127) / 128, NB);
    colsum_kernel<<<gc, 128>>>(y_real);

    dim3 gg(DD / 128, MR / 64, NB);       // 3 x 3 x 64
    mma_gemm_kernel<0><<<gg, 256, SMEM_BYTES>>>(nullptr);
    mma_gemm_kernel<1><<<gg, 256, SMEM_BYTES>>>(y);

    row192_kernel<<<gc, 128>>>(y);
}

// round 5
// speedup vs baseline: 4.1503x; 1.9100x over previous
#include <cuda_runtime.h>
#include <cuda_bf16.h>
#include <math.h>
#include <stdint.h>

#define DD 384
#define HH 192
#define NB 64
#define NATOMS 8192
#define IMG (DD*DD)
#define K1 256            // stage-1 folded K (208) padded to 256
#define MR 192            // rows 0..191 via GEMM; 192 special; 193..383 mirrored

// ---------------- device scratch -------------------------------------------
__device__ __align__(16) __nv_bfloat16 g_Cb_h[MR*K1], g_Cb_l[MR*K1];
__device__ __align__(16) __nv_bfloat16 g_Sb_h[MR*K1], g_Sb_l[MR*K1];
__device__ __align__(16) __nv_bfloat16 g_H1b_h[IMG], g_H1b_l[IMG];
__device__ __align__(16) __nv_bfloat16 g_H2b_h[IMG], g_H2b_l[IMG];
__device__ float g_H1f[IMG];
__device__ __align__(16) __nv_bfloat16 g_XeT_h[NB*DD*K1], g_XeT_l[NB*DD*K1];
__device__ __align__(16) __nv_bfloat16 g_XoT_h[NB*DD*K1], g_XoT_l[NB*DD*K1];
__device__ __align__(16) __nv_bfloat16 g_Trb_h[NB*MR*DD], g_Trb_l[NB*MR*DD];
__device__ __align__(16) __nv_bfloat16 g_Tib_h[NB*MR*DD], g_Tib_l[NB*MR*DD];
__device__ float g_T192[NB*DD];

// ---------------- helpers ----------------------------------------------------
__device__ __forceinline__ void split_bf16(float x, __nv_bfloat16& h, __nv_bfloat16& l) {
    h = __float2bfloat16_rn(x);
    l = __float2bfloat16_rn(x - __bfloat162float(h));
}
__device__ __forceinline__ uint32_t smem_u32(const void* p) {
    uint32_t a;
    asm("{ .reg .u64 t; cvta.to.shared.u64 t, %1; cvt.u32.u64 %0, t; }" : "=r"(a) : "l"(p));
    return a;
}
__device__ __forceinline__ uint32_t swz(uint32_t boff) {   // 128B-row swizzle
    return boff ^ ((boff >> 3) & 0x70);
}
__device__ __forceinline__ void ldsm_x4(uint32_t addr, uint32_t* r) {
    asm volatile("ldmatrix.sync.aligned.m8n8.x4.shared.b16 {%0,%1,%2,%3}, [%4];"
                 : "=r"(r[0]), "=r"(r[1]), "=r"(r[2]), "=r"(r[3]) : "r"(addr));
}
__device__ __forceinline__ void ldsm_x2(uint32_t addr, uint32_t* r) {
    asm volatile("ldmatrix.sync.aligned.m8n8.x2.shared.b16 {%0,%1}, [%2];"
                 : "=r"(r[0]), "=r"(r[1]) : "r"(addr));
}
__device__ __forceinline__ void mma_bf16(float* c, const uint32_t* a, const uint32_t* b) {
    asm volatile("mma.sync.aligned.m16n8k16.row.col.f32.bf16.bf16.f32 "
                 "{%0,%1,%2,%3},{%4,%5,%6,%7},{%8,%9},{%0,%1,%2,%3};"
                 : "+f"(c[0]), "+f"(c[1]), "+f"(c[2]), "+f"(c[3])
                 : "r"(a[0]), "r"(a[1]), "r"(a[2]), "r"(a[3]), "r"(b[0]), "r"(b[1]));
}
__device__ __forceinline__ void cpasync16(uint32_t dst, const void* src) {
    asm volatile("cp.async.cg.shared.global [%0], [%1], 16;" :: "r"(dst), "l"(src));
}
#define CP_COMMIT() asm volatile("cp.async.commit_group;" ::: "memory")
#define CP_WAIT(n)  asm volatile("cp.async.wait_group %0;" :: "n"(n) : "memory")
__device__ __forceinline__ void red_v4(float* addr, float a, float b, float c, float d) {
    asm volatile("red.global.add.v4.f32 [%0], {%1,%2,%3,%4};"
                 :: "l"(addr), "f"(a), "f"(b), "f"(c), "f"(d) : "memory");
}

// ---------------- table prep -------------------------------------------------
__global__ void tableA_kernel() {
    int i = blockIdx.x * blockDim.x + threadIdx.x;
    if (i >= MR * K1) return;
    int k = i >> 8, u = i & 255;
    float c = 0.f, s = 0.f;
    if (u <= 192) {
        int m = ((k + HH) * (u + HH)) % DD;
        double th = (double)m * (2.0 * M_PI / (double)DD);
        c = (float)cos(th); s = (float)sin(th);
    }
    split_bf16(c, g_Cb_h[i], g_Cb_l[i]);
    split_bf16(s, g_Sb_h[i], g_Sb_l[i]);
}
__global__ void tableH_kernel() {
    int i = blockIdx.x * blockDim.x + threadIdx.x;
    if (i >= IMG) return;
    int v = i / DD, l = i % DD;
    int m = ((v + HH) * (l + HH)) % DD;
    double th = (double)m * (2.0 * M_PI / (double)DD);
    float c = (float)cos(th), s = (float)sin(th);
    split_bf16(c + s, g_H1b_h[i], g_H1b_l[i]);
    split_bf16(c - s, g_H2b_h[i], g_H2b_l[i]);
    g_H1f[i] = c + s;
}

// ---------------- splat with red.v4 ------------------------------------------
__global__ void splat_kernel(const float* __restrict__ crd,
                             const float* __restrict__ rot,
                             const float* __restrict__ rot_init,
                             const float* __restrict__ trans_init,
                             float* __restrict__ img) {
    int gid = blockIdx.x * blockDim.x + threadIdx.x;
    if (gid >= NB * NATOMS) return;
    int b = gid >> 13;
    const float* p = crd + (size_t)gid * 3;
    float x0 = p[0], x1 = p[1], x2 = p[2];
    float c0 = x0 * __ldg(&rot_init[0]) + x1 * __ldg(&rot_init[3]) + x2 * __ldg(&rot_init[6]) + __ldg(&trans_init[0]);
    float c1 = x0 * __ldg(&rot_init[1]) + x1 * __ldg(&rot_init[4]) + x2 * __ldg(&rot_init[7]) + __ldg(&trans_init[1]);
    float c2 = x0 * __ldg(&rot_init[2]) + x1 * __ldg(&rot_init[5]) + x2 * __ldg(&rot_init[8]) + __ldg(&trans_init[2]);
    const float* R = rot + b * 9;
    float fx = c0 * __ldg(&R[0]) + c1 * __ldg(&R[1]) + c2 * __ldg(&R[2]);
    float fy = c0 * __ldg(&R[3]) + c1 * __ldg(&R[4]) + c2 * __ldg(&R[5]);
    float cx = fx + (float)HH, cy = fy + (float)HH;
    int ix0 = (int)rintf(cx) - 5, iy0 = (int)rintf(cy) - 5;
    const float inv2s2 = 1.0f / (2.0f * 1.5f * 1.5f);

    // 16-wide aligned x-window covering the valid 11-pixel support
    int base = ix0 & ~3;
    base = base < 0 ? 0 : (base > DD - 16 ? DD - 16 : base);
    float wx[16];
    float sq[4];
    bool anyx = false;
#pragma unroll
    for (int q = 0; q < 4; q++) {
        float s = 0.f;
#pragma unroll
        for (int j = 0; j < 4; j++) {
            int pos = base + q * 4 + j;
            float d = (float)pos - cx;
            bool in = (pos >= ix0) && (pos <= ix0 + 10);
            float w = in ? expf(-d * d * inv2s2) : 0.0f;
            wx[q * 4 + j] = w;
            s += w;
        }
        sq[q] = s;
        anyx |= (s != 0.f);
    }
    if (!anyx) return;

    float gy[11];
#pragma unroll
    for (int t = 0; t < 11; t++) {
        int iy = iy0 + t;
        float dy = (float)iy - cy;
        gy[t] = ((unsigned)iy < (unsigned)DD) ? expf(-dy * dy * inv2s2) : 0.0f;
    }

    float* im = img + (size_t)b * IMG;
#pragma unroll
    for (int ty = 0; ty < 11; ty++) {
        float gyv = gy[ty];
        if (gyv == 0.0f) continue;
        float* rowp = im + (iy0 + ty) * DD + base;
#pragma unroll
        for (int q = 0; q < 4; q++) {
            if (sq[q] != 0.f)
                red_v4(rowp + q * 4, gyv * wx[q*4], gyv * wx[q*4+1], gyv * wx[q*4+2], gyv * wx[q*4+3]);
        }
    }
}

// ---------------- fold + transpose X -> XeT/XoT bf16 hi/lo ------------------
__global__ void fold_kernel(const float* __restrict__ X) {
    __shared__ float se[32][33];
    __shared__ float so[32][33];
    int z = blockIdx.z;
    int u0 = blockIdx.y * 32;
    int v0 = blockIdx.x * 32;
    const float* Xb = X + (size_t)z * IMG;
#pragma unroll
    for (int r = 0; r < 4; r++) {
        int uu = u0 + threadIdx.y + r * 8;
        int vv = v0 + threadIdx.x;
        float e = 0.f, o = 0.f;
        if (uu == 0) { e = Xb[vv]; }
        else if (uu < 192) { float a = Xb[uu * DD + vv], bm = Xb[(DD - uu) * DD + vv]; e = a + bm; o = a - bm; }
        else if (uu == 192) { e = Xb[192 * DD + vv]; }
        se[threadIdx.y + r * 8][threadIdx.x] = e;
        so[threadIdx.y + r * 8][threadIdx.x] = o;
    }
    __syncthreads();
#pragma unroll
    for (int r = 0; r < 4; r++) {
        int vv = v0 + threadIdx.y + r * 8;
        int uu = u0 + threadIdx.x;
        if (uu >= 208) continue;   // pad region stays zero (zero-init globals)
        float e = se[threadIdx.x][threadIdx.y + r * 8];
        float o = so[threadIdx.x][threadIdx.y + r * 8];
        size_t off = ((size_t)z * DD + vv) * K1 + uu;
        split_bf16(e, g_XeT_h[off], g_XeT_l[off]);
        split_bf16(o, g_XoT_h[off], g_XoT_l[off]);
    }
}

// ---------------- colsum (Tr row 192) + Y row 192 ---------------------------
__global__ void colsum_kernel(const float* __restrict__ X) {
    int b = blockIdx.y;
    int v = threadIdx.x;                 // 0..383
    int u0 = blockIdx.x * 48;            // 8 chunks of 48 rows
    const float* Xb = X + (size_t)b * IMG + (size_t)u0 * DD + v;
    float acc = 0.0f;
#pragma unroll 8
    for (int u = 0; u < 48; u++) acc += Xb[u * DD];
    atomicAdd(&g_T192[b * DD + v], acc);
}
__global__ void row192_kernel(float* __restrict__ Y) {
    int b = blockIdx.y;
    int l = blockIdx.x * blockDim.x + threadIdx.x;
    if (l >= DD) return;
    const float* t = g_T192 + b * DD;
    float acc = 0.0f;
#pragma unroll 8
    for (int v = 0; v < DD; v++) acc += t[v] * g_H1f[v * DD + l];
    Y[(size_t)b * IMG + 192 * DD + l] = acc;
}

// ---------------- generic split-precision HMMA GEMM, cp.async 2-stage -------
// Block: 256 thr = 8 warps (2 M x 4 N), block tile 64x128, warp tile 32x32.
// MODE 0 (stage 1): A0=C, A1=S ; B0=XeT, B1=XoT (lda=ldb=K1) -> Tr/Ti split-write
// MODE 1 (stage 2): A0=Tr, A1=Ti ; B0=H1, B1=H2 (lda=ldb=DD) -> Y=P+Q, mirror P-Q
// smem per stage: A 4x8KB @0, B 4x16KB @32768 -> 96KB; 2 stages = 192KB.
#define STG 98304u
template<int MODE>
__global__ __launch_bounds__(256, 1) void mma_gemm_kernel(float* __restrict__ Y) {
    extern __shared__ char smem[];
    uint32_t sb = smem_u32(smem);
    const int t = threadIdx.x;
    const int lane = t & 31, wid = t >> 5;
    const int wm = wid >> 2, wn = wid & 3;
    const int z = blockIdx.z, m0 = blockIdx.y * 64, n0 = blockIdx.x * 128;

    const int KCH = (MODE == 0) ? 4 : 6;
    const int LD  = (MODE == 0) ? K1 : DD;

    const __nv_bfloat16* Asrc[4];
    const __nv_bfloat16* Bsrc[4];
    if (MODE == 0) {
        Asrc[0] = g_Cb_h + (size_t)m0 * K1;  Asrc[1] = g_Cb_l + (size_t)m0 * K1;
        Asrc[2] = g_Sb_h + (size_t)m0 * K1;  Asrc[3] = g_Sb_l + (size_t)m0 * K1;
        size_t bo = ((size_t)z * DD + n0) * K1;
        Bsrc[0] = g_XeT_h + bo; Bsrc[1] = g_XeT_l + bo;
        Bsrc[2] = g_XoT_h + bo; Bsrc[3] = g_XoT_l + bo;
    } else {
        size_t ao = ((size_t)z * MR + m0) * DD;
        Asrc[0] = g_Trb_h + ao; Asrc[1] = g_Trb_l + ao;
        Asrc[2] = g_Tib_h + ao; Asrc[3] = g_Tib_l + ao;
        size_t bo = (size_t)n0 * DD;
        Bsrc[0] = g_H1b_h + bo; Bsrc[1] = g_H1b_l + bo;
        Bsrc[2] = g_H2b_h + bo; Bsrc[3] = g_H2b_l + bo;
    }

    // async stage of one k-chunk into buffer `buf`
    auto stage = [&](uint32_t buf, int kc) {
#pragma unroll
        for (int s = 0; s < 4; s++) {
#pragma unroll
            for (int j = 0; j < 2; j++) {
                int cid = t + 256 * j;
                int row = cid >> 3, c = cid & 7;
                cpasync16(buf + s * 8192u + swz((uint32_t)row * 128u + (uint32_t)c * 16u),
                          Asrc[s] + (size_t)row * LD + kc * 64 + c * 8);
            }
#pragma unroll
            for (int j = 0; j < 4; j++) {
                int cid = t + 256 * j;
                int row = cid >> 3, c = cid & 7;
                cpasync16(buf + 32768u + s * 16384u + swz((uint32_t)row * 128u + (uint32_t)c * 16u),
                          Bsrc[s] + (size_t)row * LD + kc * 64 + c * 8);
            }
        }
    };

    float acc[2][2][4][4];
#pragma unroll
    for (int o = 0; o < 2; o++)
#pragma unroll
        for (int mt = 0; mt < 2; mt++)
#pragma unroll
            for (int nt = 0; nt < 4; nt++)
#pragma unroll
                for (int r = 0; r < 4; r++) acc[o][mt][nt][r] = 0.f;

    const int a_row = wm * 32 + (lane & 7) + ((lane >> 3) & 1) * 8;
    const int a_kb  = (lane >> 4) * 16;
    const int b_row = wn * 32 + (lane & 7);
    const int b_kb  = (((lane & 15) >> 3)) * 16;

    stage(sb, 0);
    CP_COMMIT();

    for (int kc = 0; kc < KCH; kc++) {
        uint32_t cur = sb + (uint32_t)(kc & 1) * STG;
        if (kc + 1 < KCH) {
            stage(sb + (uint32_t)((kc + 1) & 1) * STG, kc + 1);
            CP_COMMIT();
            CP_WAIT(1);
        } else {
            CP_WAIT(0);
        }
        __syncthreads();

#pragma unroll
        for (int k16 = 0; k16 < 4; k16++) {
            uint32_t a[4][2][4], b[4][4][2];
#pragma unroll
            for (int s = 0; s < 4; s++)
#pragma unroll
                for (int mt = 0; mt < 2; mt++) {
                    uint32_t bo = (uint32_t)(a_row + mt * 16) * 128u + (uint32_t)(k16 * 32 + a_kb);
                    ldsm_x4(cur + s * 8192u + swz(bo), a[s][mt]);
                }
#pragma unroll
            for (int s = 0; s < 4; s++)
#pragma unroll
                for (int nt = 0; nt < 4; nt++) {
                    uint32_t bo = (uint32_t)(b_row + nt * 8) * 128u + (uint32_t)(k16 * 32 + b_kb);
                    ldsm_x2(cur + 32768u + s * 16384u + swz(bo), b[s][nt]);
                }
#pragma unroll
            for (int mt = 0; mt < 2; mt++)
#pragma unroll
                for (int nt = 0; nt < 4; nt++) {
                    mma_bf16(acc[0][mt][nt], a[0][mt], b[0][nt]);
                    mma_bf16(acc[0][mt][nt], a[0][mt], b[1][nt]);
                    mma_bf16(acc[0][mt][nt], a[1][mt], b[0][nt]);
                    mma_bf16(acc[1][mt][nt], a[2][mt], b[2][nt]);
                    mma_bf16(acc[1][mt][nt], a[2][mt], b[3][nt]);
                    mma_bf16(acc[1][mt][nt], a[3][mt], b[2][nt]);
                }
        }
        __syncthreads();
    }

    const int gr = lane >> 2, gc = 2 * (lane & 3);
    if (MODE == 0) {
#pragma unroll
        for (int mt = 0; mt < 2; mt++)
#pragma unroll
            for (int nt = 0; nt < 4; nt++) {
                int col = n0 + wn * 32 + nt * 8 + gc;
#pragma unroll
                for (int h = 0; h < 2; h++) {
                    int row = m0 + wm * 32 + mt * 16 + gr + h * 8;
                    size_t off = ((size_t)z * MR + row) * DD + col;
                    __nv_bfloat16 h0, l0, h1, l1;
                    split_bf16(acc[0][mt][nt][h * 2],     h0, l0);
                    split_bf16(acc[0][mt][nt][h * 2 + 1], h1, l1);
                    __nv_bfloat162 hh; hh.x = h0; hh.y = h1;
                    __nv_bfloat162 ll; ll.x = l0; ll.y = l1;
                    *reinterpret_cast<__nv_bfloat162*>(&g_Trb_h[off]) = hh;
                    *reinterpret_cast<__nv_bfloat162*>(&g_Trb_l[off]) = ll;
                    split_bf16(acc[1][mt][nt][h * 2],     h0, l0);
                    split_bf16(acc[1][mt][nt][h * 2 + 1], h1, l1);
                    hh.x = h0; hh.y = h1; ll.x = l0; ll.y = l1;
                    *reinterpret_cast<__nv_bfloat162*>(&g_Tib_h[off]) = hh;
                    *reinterpret_cast<__nv_bfloat162*>(&g_Tib_l[off]) = ll;
                }
            }
    } else {
        float* Yb = Y + (size_t)z * IMG;
#pragma unroll
        for (int mt = 0; mt < 2; mt++)
#pragma unroll
            for (int nt = 0; nt < 4; nt++) {
                int col = n0 + wn * 32 + nt * 8 + gc;
#pragma unroll
                for (int h = 0; h < 2; h++) {
                    int row = m0 + wm * 32 + mt * 16 + gr + h * 8;
                    float p0 = acc[0][mt][nt][h * 2],     q0 = acc[1][mt][nt][h * 2];
                    float p1 = acc[0][mt][nt][h * 2 + 1], q1 = acc[1][mt][nt][h * 2 + 1];
                    float2 yp; yp.x = p0 + q0; yp.y = p1 + q1;
                    *reinterpret_cast<float2*>(&Yb[(size_t)row * DD + col]) = yp;
                    if (row >= 1) {
                        float2 ym; ym.x = p0 - q0; ym.y = p1 - q1;
                        *reinterpret_cast<float2*>(&Yb[(size_t)(DD - row) * DD + col]) = ym;
                    }
                }
            }
    }
}

#define SMEM_BYTES (2 * 98304)

// ---------------------------------------------------------------------------
extern "C" void kernel_launch(void* const* d_in, const int* in_sizes, int n_in,
                              void* d_out, int out_size) {
    const float* crd = nullptr;
    const float* rot = nullptr;
    const float* rot_init = nullptr;
    const float* trans_init = nullptr;
    for (int i = 0; i < n_in; i++) {
        switch (in_sizes[i]) {
            case 1572864: crd        = (const float*)d_in[i]; break;
            case 576:     rot        = (const float*)d_in[i]; break;
            case 9:       rot_init   = (const float*)d_in[i]; break;
            case 3:       trans_init = (const float*)d_in[i]; break;
            default: break;
        }
    }

    float* y = (float*)d_out;
    size_t half = (size_t)out_size / 2;   // 64*384*384
    float* y_real = y + half;

    cudaFuncSetAttribute(mma_gemm_kernel<0>, cudaFuncAttributeMaxDynamicSharedMemorySize, SMEM_BYTES);
    cudaFuncSetAttribute(mma_gemm_kernel<1>, cudaFuncAttributeMaxDynamicSharedMemorySize, SMEM_BYTES);

    cudaMemsetAsync(y_real, 0, half * sizeof(float));
    void* t192_ptr = nullptr;
    cudaGetSymbolAddress(&t192_ptr, g_T192);
    cudaMemsetAsync(t192_ptr, 0, NB * DD * sizeof(float));

    tableA_kernel<<<(MR * K1 + 255) / 256, 256>>>();
    tableH_kernel<<<(IMG + 255) / 256, 256>>>();

    splat_kernel<<<(NB * NATOMS + 255) / 256, 256>>>(crd, rot, rot_init, trans_init, y_real);

    dim3 gf(DD / 32, 7, NB);              // u tiles cover 0..223 (>=208 skipped)
    fold_kernel<<<gf, dim3(32, 8)>>>(y_real);

    dim3 gcs(8, NB);
    colsum_kernel<<<gcs, 384>>>(y_real);

    dim3 gg(DD / 128, MR / 64, NB);       // 3 x 3 x 64
    mma_gemm_kernel<0><<<gg, 256, SMEM_BYTES>>>(nullptr);
    mma_gemm_kernel<1><<<gg, 256, SMEM_BYTES>>>(y);

    dim3 gr((DD + 127) / 128, NB);
    row192_kernel<<<gr, 128>>>(y);
}

// round 7
// speedup vs baseline: 4.4338x; 1.0683x over previous
#include <cuda_runtime.h>
#include <cuda_bf16.h>
#include <math.h>
#include <stdint.h>

#define DD 384
#define HH 192
#define NB 64
#define NATOMS 8192
#define IMG (DD*DD)
#define K1 256            // stage-1 folded K (208) padded to 256
#define MR 192            // rows 0..191 via GEMM; 192 special; 193..383 mirrored

// ---------------- device scratch -------------------------------------------
__device__ float g_sinf[DD];
__device__ __align__(16) __nv_bfloat16 g_Cb_h[MR*K1], g_Cb_l[MR*K1];
__device__ __align__(16) __nv_bfloat16 g_Sb_h[MR*K1], g_Sb_l[MR*K1];
__device__ __align__(16) __nv_bfloat16 g_H1b_h[IMG], g_H1b_l[IMG];
__device__ __align__(16) __nv_bfloat16 g_H2b_h[IMG], g_H2b_l[IMG];
__device__ float g_H1f[IMG];
__device__ __align__(16) __nv_bfloat16 g_XeT_h[NB*DD*K1], g_XeT_l[NB*DD*K1];
__device__ __align__(16) __nv_bfloat16 g_XoT_h[NB*DD*K1], g_XoT_l[NB*DD*K1];
__device__ __align__(16) __nv_bfloat16 g_Trb_h[NB*MR*DD], g_Trb_l[NB*MR*DD];
__device__ __align__(16) __nv_bfloat16 g_Tib_h[NB*MR*DD], g_Tib_l[NB*MR*DD];
__device__ float g_T192[NB*DD];

// ---------------- helpers ----------------------------------------------------
__device__ __forceinline__ void split_bf16(float x, __nv_bfloat16& h, __nv_bfloat16& l) {
    h = __float2bfloat16_rn(x);
    l = __float2bfloat16_rn(x - __bfloat162float(h));
}
__device__ __forceinline__ uint32_t smem_u32(const void* p) {
    uint32_t a;
    asm("{ .reg .u64 t; cvta.to.shared.u64 t, %1; cvt.u32.u64 %0, t; }" : "=r"(a) : "l"(p));
    return a;
}
__device__ __forceinline__ uint32_t swz(uint32_t boff) {
    return boff ^ ((boff >> 3) & 0x70);
}
__device__ __forceinline__ void ldsm_x4(uint32_t addr, uint32_t* r) {
    asm volatile("ldmatrix.sync.aligned.m8n8.x4.shared.b16 {%0,%1,%2,%3}, [%4];"
                 : "=r"(r[0]), "=r"(r[1]), "=r"(r[2]), "=r"(r[3]) : "r"(addr));
}
__device__ __forceinline__ void ldsm_x2(uint32_t addr, uint32_t* r) {
    asm volatile("ldmatrix.sync.aligned.m8n8.x2.shared.b16 {%0,%1}, [%2];"
                 : "=r"(r[0]), "=r"(r[1]) : "r"(addr));
}
__device__ __forceinline__ void mma_bf16(float* c, const uint32_t* a, const uint32_t* b) {
    asm volatile("mma.sync.aligned.m16n8k16.row.col.f32.bf16.bf16.f32 "
                 "{%0,%1,%2,%3},{%4,%5,%6,%7},{%8,%9},{%0,%1,%2,%3};"
                 : "+f"(c[0]), "+f"(c[1]), "+f"(c[2]), "+f"(c[3])
                 : "r"(a[0]), "r"(a[1]), "r"(a[2]), "r"(a[3]), "r"(b[0]), "r"(b[1]));
}
__device__ __forceinline__ void cpasync16(uint32_t dst, const void* src) {
    asm volatile("cp.async.cg.shared.global [%0], [%1], 16;" :: "r"(dst), "l"(src));
}
#define CP_COMMIT() asm volatile("cp.async.commit_group;" ::: "memory")
#define CP_WAIT(n)  asm volatile("cp.async.wait_group %0;" :: "n"(n) : "memory")
__device__ __forceinline__ void red_v4(float* addr, float a, float b, float c, float d) {
    asm volatile("red.global.add.v4.f32 [%0], {%1,%2,%3,%4};"
                 :: "l"(addr), "f"(a), "f"(b), "f"(c), "f"(d) : "memory");
}

// ---------------- tiny sin table (double trig once) --------------------------
__global__ void sintab_kernel() {
    int i = threadIdx.x;
    if (i < DD) g_sinf[i] = (float)sin((double)i * (2.0 * M_PI / (double)DD));
}

// ---------------- all trig tables via gather ---------------------------------
__global__ void tables_kernel() {
    int i = blockIdx.x * blockDim.x + threadIdx.x;
    if (i < MR * K1) {
        int k = i >> 8, u = i & 255;
        float c = 0.f, s = 0.f;
        if (u <= 192) {
            int m = ((k + HH) * (u + HH)) % DD;
            s = g_sinf[m];
            c = g_sinf[(m + 96) % DD];
        }
        split_bf16(c, g_Cb_h[i], g_Cb_l[i]);
        split_bf16(s, g_Sb_h[i], g_Sb_l[i]);
    } else {
        int j = i - MR * K1;
        if (j >= IMG) return;
        int v = j / DD, l = j % DD;
        int m = ((v + HH) * (l + HH)) % DD;
        float s = g_sinf[m];
        float c = g_sinf[(m + 96) % DD];
        split_bf16(c + s, g_H1b_h[j], g_H1b_l[j]);
        split_bf16(c - s, g_H2b_h[j], g_H2b_l[j]);
        g_H1f[j] = c + s;
    }
}

// ---------------- splat with red.v4 ------------------------------------------
__global__ void splat_kernel(const float* __restrict__ crd,
                             const float* __restrict__ rot,
                             const float* __restrict__ rot_init,
                             const float* __restrict__ trans_init,
                             float* __restrict__ img) {
    int gid = blockIdx.x * blockDim.x + threadIdx.x;
    if (gid >= NB * NATOMS) return;
    int b = gid >> 13;
    const float* p = crd + (size_t)gid * 3;
    float x0 = p[0], x1 = p[1], x2 = p[2];
    float c0 = x0 * __ldg(&rot_init[0]) + x1 * __ldg(&rot_init[3]) + x2 * __ldg(&rot_init[6]) + __ldg(&trans_init[0]);
    float c1 = x0 * __ldg(&rot_init[1]) + x1 * __ldg(&rot_init[4]) + x2 * __ldg(&rot_init[7]) + __ldg(&trans_init[1]);
    float c2 = x0 * __ldg(&rot_init[2]) + x1 * __ldg(&rot_init[5]) + x2 * __ldg(&rot_init[8]) + __ldg(&trans_init[2]);
    const float* R = rot + b * 9;
    float fx = c0 * __ldg(&R[0]) + c1 * __ldg(&R[1]) + c2 * __ldg(&R[2]);
    float fy = c0 * __ldg(&R[3]) + c1 * __ldg(&R[4]) + c2 * __ldg(&R[5]);
    float cx = fx + (float)HH, cy = fy + (float)HH;
    int ix0 = (int)rintf(cx) - 5, iy0 = (int)rintf(cy) - 5;
    const float inv2s2 = 1.0f / (2.0f * 1.5f * 1.5f);

    int base = ix0 & ~3;
    base = base < 0 ? 0 : (base > DD - 16 ? DD - 16 : base);
    float wx[16];
    float sq[4];
    bool anyx = false;
#pragma unroll
    for (int q = 0; q < 4; q++) {
        float s = 0.f;
#pragma unroll
        for (int j = 0; j < 4; j++) {
            int pos = base + q * 4 + j;
            float d = (float)pos - cx;
            bool in = (pos >= ix0) && (pos <= ix0 + 10);
            float w = in ? __expf(-d * d * inv2s2) : 0.0f;
            wx[q * 4 + j] = w;
            s += w;
        }
        sq[q] = s;
        anyx |= (s != 0.f);
    }
    if (!anyx) return;

    float gy[11];
#pragma unroll
    for (int t = 0; t < 11; t++) {
        int iy = iy0 + t;
        float dy = (float)iy - cy;
        gy[t] = ((unsigned)iy < (unsigned)DD) ? __expf(-dy * dy * inv2s2) : 0.0f;
    }

    float* im = img + (size_t)b * IMG;
#pragma unroll
    for (int ty = 0; ty < 11; ty++) {
        float gyv = gy[ty];
        if (gyv == 0.0f) continue;
        float* rowp = im + (iy0 + ty) * DD + base;
#pragma unroll
        for (int q = 0; q < 4; q++) {
            if (sq[q] != 0.f)
                red_v4(rowp + q * 4, gyv * wx[q*4], gyv * wx[q*4+1], gyv * wx[q*4+2], gyv * wx[q*4+3]);
        }
    }
}

// ---------------- fold + transpose X -> XeT/XoT (+ fused colsum) -------------
__global__ void fold_kernel(const float* __restrict__ X) {
    __shared__ float se[32][33];
    __shared__ float so[32][33];
    int z = blockIdx.z;
    int u0 = blockIdx.y * 32;
    int v0 = blockIdx.x * 32;
    const float* Xb = X + (size_t)z * IMG;
#pragma unroll
    for (int r = 0; r < 4; r++) {
        int uu = u0 + threadIdx.y + r * 8;
        int vv = v0 + threadIdx.x;
        float e = 0.f, o = 0.f;
        if (uu == 0) { e = Xb[vv]; }
        else if (uu < 192) { float a = Xb[uu * DD + vv], bm = Xb[(DD - uu) * DD + vv]; e = a + bm; o = a - bm; }
        else if (uu == 192) { e = Xb[192 * DD + vv]; }
        se[threadIdx.y + r * 8][threadIdx.x] = e;
        so[threadIdx.y + r * 8][threadIdx.x] = o;
    }
    __syncthreads();
    // fused colsum: sum_u X[u][v] == sum of folded e over u=0..192
    if (threadIdx.y == 0) {
        int vv = v0 + threadIdx.x;
        float acc = 0.f;
#pragma unroll
        for (int i = 0; i < 32; i++) acc += se[i][threadIdx.x];
        if (acc != 0.f || u0 == 0) atomicAdd(&g_T192[z * DD + vv], acc);
    }
#pragma unroll
    for (int r = 0; r < 4; r++) {
        int vv = v0 + threadIdx.y + r * 8;
        int uu = u0 + threadIdx.x;
        if (uu >= 208) continue;
        float e = se[threadIdx.x][threadIdx.y + r * 8];
        float o = so[threadIdx.x][threadIdx.y + r * 8];
        size_t off = ((size_t)z * DD + vv) * K1 + uu;
        split_bf16(e, g_XeT_h[off], g_XeT_l[off]);
        split_bf16(o, g_XoT_h[off], g_XoT_l[off]);
    }
}

// ---------------- row 192 of Y ------------------------------------------------
__global__ void row192_kernel(float* __restrict__ Y) {
    int b = blockIdx.y;
    int l = blockIdx.x * blockDim.x + threadIdx.x;
    if (l >= DD) return;
    const float* t = g_T192 + b * DD;
    float acc = 0.0f;
#pragma unroll 8
    for (int v = 0; v < DD; v++) acc += t[v] * g_H1f[v * DD + l];
    Y[(size_t)b * IMG + 192 * DD + l] = acc;
}

// ---------------- generic split-precision HMMA GEMM, cp.async 2-stage -------
// MODE 0 (stage 1): A0=C, A1=S ; B0=XeT, B1=XoT (K=256 folded) -> Tr/Ti bf16 split
// MODE 1 (stage 2): A0=Tr, A1=Ti ; B0=H1, B1=H2 (K=384)        -> Y=P+Q, mirror P-Q
#define STG 98304u
template<int MODE>
__global__ __launch_bounds__(256, 1) void mma_gemm_kernel(float* __restrict__ Y) {
    extern __shared__ char smem[];
    uint32_t sb = smem_u32(smem);
    const int t = threadIdx.x;
    const int lane = t & 31, wid = t >> 5;
    const int wm = wid >> 2, wn = wid & 3;
    const int z = blockIdx.z, m0 = blockIdx.y * 64, n0 = blockIdx.x * 128;

    const int KCH = (MODE == 0) ? 4 : 6;
    const int LD  = (MODE == 0) ? K1 : DD;

    const __nv_bfloat16* Asrc[4];
    const __nv_bfloat16* Bsrc[4];
    if (MODE == 0) {
        Asrc[0] = g_Cb_h + (size_t)m0 * K1;  Asrc[1] = g_Cb_l + (size_t)m0 * K1;
        Asrc[2] = g_Sb_h + (size_t)m0 * K1;  Asrc[3] = g_Sb_l + (size_t)m0 * K1;
        size_t bo = ((size_t)z * DD + n0) * K1;
        Bsrc[0] = g_XeT_h + bo; Bsrc[1] = g_XeT_l + bo;
        Bsrc[2] = g_XoT_h + bo; Bsrc[3] = g_XoT_l + bo;
    } else {
        size_t ao = ((size_t)z * MR + m0) * DD;
        Asrc[0] = g_Trb_h + ao; Asrc[1] = g_Trb_l + ao;
        Asrc[2] = g_Tib_h + ao; Asrc[3] = g_Tib_l + ao;
        size_t bo = (size_t)n0 * DD;
        Bsrc[0] = g_H1b_h + bo; Bsrc[1] = g_H1b_l + bo;
        Bsrc[2] = g_H2b_h + bo; Bsrc[3] = g_H2b_l + bo;
    }

    auto stage = [&](uint32_t buf, int kc) {
#pragma unroll
        for (int s = 0; s < 4; s++) {
#pragma unroll
            for (int j = 0; j < 2; j++) {
                int cid = t + 256 * j;
                int row = cid >> 3, c = cid & 7;
                cpasync16(buf + s * 8192u + swz((uint32_t)row * 128u + (uint32_t)c * 16u),
                          Asrc[s] + (size_t)row * LD + kc * 64 + c * 8);
            }
#pragma unroll
            for (int j = 0; j < 4; j++) {
                int cid = t + 256 * j;
                int row = cid >> 3, c = cid & 7;
                cpasync16(buf + 32768u + s * 16384u + swz((uint32_t)row * 128u + (uint32_t)c * 16u),
                          Bsrc[s] + (size_t)row * LD + kc * 64 + c * 8);
            }
        }
    };

    float acc[2][2][4][4];
#pragma unroll
    for (int o = 0; o < 2; o++)
#pragma unroll
        for (int mt = 0; mt < 2; mt++)
#pragma unroll
            for (int nt = 0; nt < 4; nt++)
#pragma unroll
                for (int r = 0; r < 4; r++) acc[o][mt][nt][r] = 0.f;

    const int a_row = wm * 32 + (lane & 7) + ((lane >> 3) & 1) * 8;
    const int a_kb  = (lane >> 4) * 16;
    const int b_row = wn * 32 + (lane & 7);
    const int b_kb  = (((lane & 15) >> 3)) * 16;

    stage(sb, 0);
    CP_COMMIT();

    for (int kc = 0; kc < KCH; kc++) {
        uint32_t cur = sb + (uint32_t)(kc & 1) * STG;
        if (kc + 1 < KCH) {
            stage(sb + (uint32_t)((kc + 1) & 1) * STG, kc + 1);
            CP_COMMIT();
            CP_WAIT(1);
        } else {
            CP_WAIT(0);
        }
        __syncthreads();

#pragma unroll
        for (int k16 = 0; k16 < 4; k16++) {
            uint32_t a[4][2][4], b[4][4][2];
#pragma unroll
            for (int s = 0; s < 4; s++)
#pragma unroll
                for (int mt = 0; mt < 2; mt++) {
                    uint32_t bo = (uint32_t)(a_row + mt * 16) * 128u + (uint32_t)(k16 * 32 + a_kb);
                    ldsm_x4(cur + s * 8192u + swz(bo), a[s][mt]);
                }
#pragma unroll
            for (int s = 0; s < 4; s++)
#pragma unroll
                for (int nt = 0; nt < 4; nt++) {
                    uint32_t bo = (uint32_t)(b_row + nt * 8) * 128u + (uint32_t)(k16 * 32 + b_kb);
                    ldsm_x2(cur + 32768u + s * 16384u + swz(bo), b[s][nt]);
                }
#pragma unroll
            for (int mt = 0; mt < 2; mt++)
#pragma unroll
                for (int nt = 0; nt < 4; nt++) {
                    mma_bf16(acc[0][mt][nt], a[0][mt], b[0][nt]);
                    mma_bf16(acc[0][mt][nt], a[0][mt], b[1][nt]);
                    mma_bf16(acc[0][mt][nt], a[1][mt], b[0][nt]);
                    mma_bf16(acc[1][mt][nt], a[2][mt], b[2][nt]);
                    mma_bf16(acc[1][mt][nt], a[2][mt], b[3][nt]);
                    mma_bf16(acc[1][mt][nt], a[3][mt], b[2][nt]);
                }
        }
        __syncthreads();
    }

    const int gr = lane >> 2, gc = 2 * (lane & 3);
    if (MODE == 0) {
#pragma unroll
        for (int mt = 0; mt < 2; mt++)
#pragma unroll
            for (int nt = 0; nt < 4; nt++) {
                int col = n0 + wn * 32 + nt * 8 + gc;
#pragma unroll
                for (int h = 0; h < 2; h++) {
                    int row = m0 + wm * 32 + mt * 16 + gr + h * 8;
                    size_t off = ((size_t)z * MR + row) * DD + col;
                    __nv_bfloat16 h0, l0, h1, l1;
                    split_bf16(acc[0][mt][nt][h * 2],     h0, l0);
                    split_bf16(acc[0][mt][nt][h * 2 + 1], h1, l1);
                    __nv_bfloat162 hh; hh.x = h0; hh.y = h1;
                    __nv_bfloat162 ll; ll.x = l0; ll.y = l1;
                    *reinterpret_cast<__nv_bfloat162*>(&g_Trb_h[off]) = hh;
                    *reinterpret_cast<__nv_bfloat162*>(&g_Trb_l[off]) = ll;
                    split_bf16(acc[1][mt][nt][h * 2],     h0, l0);
                    split_bf16(acc[1][mt][nt][h * 2 + 1], h1, l1);
                    hh.x = h0; hh.y = h1; ll.x = l0; ll.y = l1;
                    *reinterpret_cast<__nv_bfloat162*>(&g_Tib_h[off]) = hh;
                    *reinterpret_cast<__nv_bfloat162*>(&g_Tib_l[off]) = ll;
                }
            }
    } else {
        float* Yb = Y + (size_t)z * IMG;
#pragma unroll
        for (int mt = 0; mt < 2; mt++)
#pragma unroll
            for (int nt = 0; nt < 4; nt++) {
                int col = n0 + wn * 32 + nt * 8 + gc;
#pragma unroll
                for (int h = 0; h < 2; h++) {
                    int row = m0 + wm * 32 + mt * 16 + gr + h * 8;
                    float p0 = acc[0][mt][nt][h * 2],     q0 = acc[1][mt][nt][h * 2];
                    float p1 = acc[0][mt][nt][h * 2 + 1], q1 = acc[1][mt][nt][h * 2 + 1];
                    float2 yp; yp.x = p0 + q0; yp.y = p1 + q1;
                    *reinterpret_cast<float2*>(&Yb[(size_t)row * DD + col]) = yp;
                    if (row >= 1) {
                        float2 ym; ym.x = p0 - q0; ym.y = p1 - q1;
                        *reinterpret_cast<float2*>(&Yb[(size_t)(DD - row) * DD + col]) = ym;
                    }
                }
            }
    }
}

#define SMEM_BYTES (2 * 98304)

// ---------------------------------------------------------------------------
extern "C" void kernel_launch(void* const* d_in, const int* in_sizes, int n_in,
                              void* d_out, int out_size) {
    const float* crd = nullptr;
    const float* rot = nullptr;
    const float* rot_init = nullptr;
    const float* trans_init = nullptr;
    for (int i = 0; i < n_in; i++) {
        switch (in_sizes[i]) {
            case 1572864: crd        = (const float*)d_in[i]; break;
            case 576:     rot        = (const float*)d_in[i]; break;
            case 9:       rot_init   = (const float*)d_in[i]; break;
            case 3:       trans_init = (const float*)d_in[i]; break;
            default: break;
        }
    }

    float* y = (float*)d_out;
    size_t half = (size_t)out_size / 2;   // 64*384*384
    float* y_real = y + half;

    cudaFuncSetAttribute(mma_gemm_kernel<0>, cudaFuncAttributeMaxDynamicSharedMemorySize, SMEM_BYTES);
    cudaFuncSetAttribute(mma_gemm_kernel<1>, cudaFuncAttributeMaxDynamicSharedMemorySize, SMEM_BYTES);

    cudaMemsetAsync(y_real, 0, half * sizeof(float));
    void* t192_ptr = nullptr;
    cudaGetSymbolAddress(&t192_ptr, g_T192);
    cudaMemsetAsync(t192_ptr, 0, NB * DD * sizeof(float));

    sintab_kernel<<<1, 384>>>();
    tables_kernel<<<(MR * K1 + IMG + 255) / 256, 256>>>();

    splat_kernel<<<(NB * NATOMS + 255) / 256, 256>>>(crd, rot, rot_init, trans_init, y_real);

    dim3 gf(DD / 32, 7, NB);
    fold_kernel<<<gf, dim3(32, 8)>>>(y_real);

    dim3 gg(DD / 128, MR / 64, NB);       // 3 x 3 x 64
    mma_gemm_kernel<0><<<gg, 256, SMEM_BYTES>>>(nullptr);
    mma_gemm_kernel<1><<<gg, 256, SMEM_BYTES>>>(y);

    dim3 gr((DD + 127) / 128, NB);
    row192_kernel<<<gr, 128>>>(y);
}